// round 3
// baseline (speedup 1.0000x reference)
#include <cuda_runtime.h>
#include <cuda_bf16.h>

// AnnularPhotonicTransferMatrix: reflectance of a 6-layer annular stack,
// TE mode, m=0, via Numerical-Recipes Bessel rational approximations.
//
// Structure exploited:
//  * each shell transfer matrix is [[a, i b],[i c, d]] with a,b,c,d REAL;
//    this form is closed under multiplication -> whole chain in real math.
//  * big-x branch: xx1 = xx0 - pi/2 -> one sincos serves J0/Y0/J1/Y1.
//  * c2 = conj(c1); c1_1 unused by the reference formula.

#define PI_2f       1.5707963267948966f
#define TWO_OVER_PI 0.636619772f

__device__ __forceinline__ void bessel4(float x, float& j0v, float& j1v,
                                        float& y0v, float& y1v) {
    if (x < 8.0f) {
        float y = x * x;
        // J0
        float n0 = ((((-184.9052456f*y + 77392.33017f)*y - 11214424.18f)*y
                     + 651619640.7f)*y - 13362590354.0f)*y + 57568490574.0f;
        float d0 = ((((y + 267.8532712f)*y + 59272.64853f)*y + 9494680.718f)*y
                     + 1029532985.0f)*y + 57568490411.0f;
        j0v = __fdividef(n0, d0);
        // J1
        float n1 = x * (((((-30.16036606f*y + 15704.48260f)*y - 2972611.439f)*y
                     + 242396853.1f)*y - 7895059235.0f)*y + 72362614232.0f);
        float d1 = ((((y + 376.9991397f)*y + 99447.43394f)*y + 18583304.74f)*y
                     + 2300535178.0f)*y + 144725228442.0f;
        j1v = __fdividef(n1, d1);
        float lg = __logf(x);
        // Y0
        float n2 = ((((228.4622733f*y - 86327.92757f)*y + 10879881.29f)*y
                     - 512359803.6f)*y + 7062834065.0f)*y - 2957821389.0f;
        float d2 = ((((y + 226.1030244f)*y + 47447.26470f)*y + 7189466.438f)*y
                     + 745249964.8f)*y + 40076544269.0f;
        y0v = __fdividef(n2, d2) + TWO_OVER_PI * j0v * lg;
        // Y1
        float n3 = x * (((((8.511937935e4f*y - 4.237922726e7f)*y + 7.349264551e9f)*y
                     - 5.153438139e11f)*y + 1.275274390e13f)*y - 4.900604943e13f);
        float d3 = (((((y + 3.549632885e3f)*y + 1.020426050e6f)*y + 2.245904002e8f)*y
                     + 3.733650367e10f)*y + 4.244419664e12f)*y + 2.499580570e14f;
        y1v = __fdividef(n3, d3) + TWO_OVER_PI * (j1v * lg - __fdividef(1.0f, x));
    } else {
        float z  = __fdividef(8.0f, x);
        float y2 = z * z;
        float s, c;
        sincosf(x - 0.785398164f, &s, &c);   // accurate reduction (x up to ~320)
        float amp = sqrtf(__fdividef(TWO_OVER_PI, x));
        float p0 = (((0.2093887211e-6f*y2 - 0.2073370639e-5f)*y2
                     + 0.2734510407e-4f)*y2 - 0.1098628627e-2f)*y2 + 1.0f;
        float q0 = (((-0.934935152e-7f*y2 + 0.7621095161e-6f)*y2
                     - 0.6911147651e-5f)*y2 + 0.1430488765e-3f)*y2 - 0.1562499995e-1f;
        float p1 = (((-0.240337019e-6f*y2 + 0.2457520174e-5f)*y2
                     - 0.3516396496e-4f)*y2 + 0.183105e-2f)*y2 + 1.0f;
        float q1 = (((0.105787412e-6f*y2 - 0.88228987e-6f)*y2
                     + 0.8449199096e-5f)*y2 - 0.2002690873e-3f)*y2 + 0.04687499995f;
        j0v = amp * (c * p0 - z * s * q0);
        y0v = amp * (s * p0 + z * c * q0);
        // xx1 = xx0 - pi/2 : cos(xx1)=s, sin(xx1)=-c
        j1v = amp * (s * p1 + z * c * q1);
        y1v = amp * (-c * p1 + z * s * q1);
    }
}

// Real quartet (a,b,c,d) of the single-shell matrix [[a, ib],[ic, d]].
__device__ __forceinline__ void shell_matrix(float k, float p, float r0, float r1,
                                             float& a, float& b, float& c, float& d) {
    float x0 = k * r0, x1 = k * r1;
    float ja, j1a, ya, y1a, jb, j1b, yb, y1b;
    bessel4(x0, ja, j1a, ya, y1a);
    bessel4(x1, jb, j1b, yb, y1b);
    float pref = PI_2f * x0;
    a = pref * (j1a * yb - y1a * jb);                     // m00 (real)
    b = __fdividef(pref, p) * (ja * yb - ya * jb);        // m01 = i*b
    c = -p * pref * (y1a * j1b - j1a * y1b);              // m10 = i*c
    d = pref * (ya * j1b - ja * y1b);                     // m11 (real)
}

// c1(z) = -(J1 + iY1)/(J0 + iY0); returns (re, im). c2 = conj(c1).
__device__ __forceinline__ float2 c_factor1(float z) {
    float j0v, j1v, y0v, y1v;
    bessel4(z, j0v, j1v, y0v, y1v);
    float inv = __fdividef(1.0f, j0v * j0v + y0v * y0v);
    float ur = -j1v, ui = -y1v;
    float2 r;
    r.x = (ur * j0v + ui * y0v) * inv;
    r.y = (ui * j0v - ur * y0v) * inv;
    return r;
}

__global__ void __launch_bounds__(256)
annular_tm_kernel(const float* __restrict__ omega,
                  const float* __restrict__ eps,
                  const float* __restrict__ mu,
                  const float* __restrict__ rho,
                  float* __restrict__ out, int W) {
    int i = blockIdx.x * blockDim.x + threadIdx.x;
    if (i >= W) return;

    const int L = 6;
    float w = omega[i];

    // rho broadcast (uniform across warp, L2-cached)
    float r_in[L], r_out[L];
    #pragma unroll
    for (int l = 0; l < L; l++) { r_in[l] = __ldg(&rho[2*l]); r_out[l] = __ldg(&rho[2*l + 1]); }

    // Chain of shells 1..4
    float A, B, C, D;
    {
        float e = eps[1 * W + i], m = mu[1 * W + i];
        float k = w * sqrtf(e * m);
        float p = sqrtf(__fdividef(e, m));
        shell_matrix(k, p, r_in[1], r_out[1], A, B, C, D);
    }
    #pragma unroll
    for (int l = 2; l <= 4; l++) {
        float e = eps[l * W + i], m = mu[l * W + i];
        float k = w * sqrtf(e * m);
        float p = sqrtf(__fdividef(e, m));
        float a, b, c, d;
        shell_matrix(k, p, r_in[l], r_out[l], a, b, c, d);
        // [[A,iB],[iC,D]] * [[a,ib],[ic,d]]
        float A2 =  A * a - B * c;
        float B2 =  A * b + B * d;
        float C2 =  C * a + D * c;
        float D2 = -C * b + D * d;
        A = A2; B = B2; C = C2; D = D2;
    }

    // Boundary media
    float e0 = eps[0 * W + i], m0 = mu[0 * W + i];
    float eL = eps[5 * W + i], mL = mu[5 * W + i];
    float k0 = w * sqrtf(e0 * m0), p0 = sqrtf(__fdividef(e0, m0));
    float kL = w * sqrtf(eL * mL), pL = sqrtf(__fdividef(eL, mL));

    float2 c01 = c_factor1(k0 * r_out[0]);     // c0_1
    float2 c02 = make_float2(c01.x, -c01.y);   // c0_2 = conj
    float2 c1a = c_factor1(kL * r_in[5]);
    float2 c12 = make_float2(c1a.x, -c1a.y);   // c1_2 = conj

    // num = iC + i*p0*c02*A - i*pL*c12*(D - p0*c02*B)
    float Tr = D - p0 * c02.x * B;
    float Ti =    -p0 * c02.y * B;
    float Vr = c12.x * Tr - c12.y * Ti;        // c12 * T
    float Vi = c12.x * Ti + c12.y * Tr;
    float Ur = -pL * Vi;                       // i*pL*V
    float Ui =  pL * Vr;
    float numr = -p0 * A * c02.y - Ur;
    float numi =  C + p0 * A * c02.x - Ui;

    // den = -i*p0*c01*A - iC - i*pL*c12*(p0*c01*B - D)
    float Sr = p0 * c01.x * B - D;
    float Si = p0 * c01.y * B;
    float Wr = c12.x * Sr - c12.y * Si;
    float Wi = c12.x * Si + c12.y * Sr;
    float Xr = -pL * Wi;
    float Xi =  pL * Wr;
    float denr =  p0 * A * c01.y - Xr;
    float deni = -p0 * A * c01.x - C - Xi;

    float R = (numr * numr + numi * numi) *
              __fdividef(1.0f, denr * denr + deni * deni);
    out[i] = R;
}

extern "C" void kernel_launch(void* const* d_in, const int* in_sizes, int n_in,
                              void* d_out, int out_size) {
    const float* omega = (const float*)d_in[0];
    const float* eps   = (const float*)d_in[1];
    const float* mu    = (const float*)d_in[2];
    const float* rho   = (const float*)d_in[3];
    float* out = (float*)d_out;
    int W = in_sizes[0];
    int threads = 256;
    int blocks = (W + threads - 1) / threads;
    annular_tm_kernel<<<blocks, threads>>>(omega, eps, mu, rho, out, W);
}

// round 4
// speedup vs baseline: 1.1128x; 1.1128x over previous
#include <cuda_runtime.h>
#include <cuda_bf16.h>

// AnnularPhotonicTransferMatrix — packed f32x2 implementation.
// Two elements per thread (i and i+W/2) carried in b64 "pf" registers;
// all polynomial / matrix math uses fma.rn.f32x2 (FFMA2) for 2x fp32 issue rate.
// Branchless small/big Bessel merge (mask blend); custom packed sincos;
// rsqrt-based reciprocals to minimize MUFU traffic.

#define PI_2f        1.5707963267948966f
#define TWO_OVER_PI  0.636619772f
#define SQRT_2_PI    0.7978845608028654f   // sqrt(2/pi)
#define MAGICF       12582912.0f           // 1.5 * 2^23

struct pf { unsigned long long v; };

__device__ __forceinline__ pf pk2(float a, float b) {
    pf r; asm("mov.b64 %0, {%1, %2};" : "=l"(r.v) : "f"(a), "f"(b)); return r;
}
__device__ __forceinline__ void up2(pf x, float& a, float& b) {
    asm("mov.b64 {%0, %1}, %2;" : "=f"(a), "=f"(b) : "l"(x.v));
}
__device__ __forceinline__ pf pc(float c) { return pk2(c, c); }
__device__ __forceinline__ pf pfma(pf a, pf b, pf c) {
    pf r; asm("fma.rn.f32x2 %0, %1, %2, %3;" : "=l"(r.v) : "l"(a.v), "l"(b.v), "l"(c.v)); return r;
}
__device__ __forceinline__ pf pmul(pf a, pf b) {
    pf r; asm("mul.rn.f32x2 %0, %1, %2;" : "=l"(r.v) : "l"(a.v), "l"(b.v)); return r;
}
__device__ __forceinline__ pf padd(pf a, pf b) {
    pf r; asm("add.rn.f32x2 %0, %1, %2;" : "=l"(r.v) : "l"(a.v), "l"(b.v)); return r;
}
__device__ __forceinline__ pf pneg(pf a) {
    pf r; asm("xor.b64 %0, %1, 0x8000000080000000;" : "=l"(r.v) : "l"(a.v)); return r;
}
// a - b  (one packed op)
__device__ __forceinline__ pf psub(pf a, pf b) { return pfma(b, pc(-1.0f), a); }

// quadrant fixup for sin/cos(r + n*pi/2)
__device__ __forceinline__ void quadfix(int n, float s, float c, float& S, float& C) {
    float ss = (n & 1) ? c : s;
    float cc = (n & 1) ? s : c;
    S = (n & 2)       ? -ss : ss;
    C = ((n + 1) & 2) ? -cc : cc;
}

// Packed J0,J1,Y0,Y1 at two x values (branchless small/big blend).
__device__ __forceinline__ void bessel4_pair(pf px, pf& J0, pf& J1, pf& Y0, pf& Y1) {
    float x0, x1; up2(px, x0, x1);
    // scalar MUFU work
    float rs0 = rsqrtf(x0), rs1 = rsqrtf(x1);
    float lga = __log2f(x0), lgb = __log2f(x1);
    pf rs = pk2(rs0, rs1);
    pf rx = pmul(rs, rs);                         // ~1/x (err ~3e-7 rel)
    pf lg = pmul(pk2(lga, lgb), pc(0.6931471806f)); // ln(x)

    // ---------- small path (y clamped so big lanes stay finite) ----------
    pf xs = pk2(fminf(x0, 8.0f), fminf(x1, 8.0f));
    pf y  = pmul(xs, xs);
    pf n0 = pfma(pfma(pfma(pfma(pfma(pc(-184.9052456f), y, pc(77392.33017f)), y,
                pc(-11214424.18f)), y, pc(651619640.7f)), y, pc(-13362590354.0f)), y,
                pc(57568490574.0f));
    pf d0 = pfma(pfma(pfma(pfma(padd(y, pc(267.8532712f)), y, pc(59272.64853f)), y,
                pc(9494680.718f)), y, pc(1029532985.0f)), y, pc(57568490411.0f));
    pf n1 = pmul(xs, pfma(pfma(pfma(pfma(pfma(pc(-30.16036606f), y, pc(15704.48260f)), y,
                pc(-2972611.439f)), y, pc(242396853.1f)), y, pc(-7895059235.0f)), y,
                pc(72362614232.0f)));
    pf d1 = pfma(pfma(pfma(pfma(padd(y, pc(376.9991397f)), y, pc(99447.43394f)), y,
                pc(18583304.74f)), y, pc(2300535178.0f)), y, pc(144725228442.0f));
    pf n2 = pfma(pfma(pfma(pfma(pfma(pc(228.4622733f), y, pc(-86327.92757f)), y,
                pc(10879881.29f)), y, pc(-512359803.6f)), y, pc(7062834065.0f)), y,
                pc(-2957821389.0f));
    pf d2 = pfma(pfma(pfma(pfma(padd(y, pc(226.1030244f)), y, pc(47447.26470f)), y,
                pc(7189466.438f)), y, pc(745249964.8f)), y, pc(40076544269.0f));
    pf n3 = pmul(xs, pfma(pfma(pfma(pfma(pfma(pc(8.511937935e4f), y, pc(-4.237922726e7f)), y,
                pc(7.349264551e9f)), y, pc(-5.153438139e11f)), y, pc(1.275274390e13f)), y,
                pc(-4.900604943e13f)));
    pf d3 = pfma(pfma(pfma(pfma(pfma(padd(y, pc(3.549632885e3f)), y, pc(1.020426050e6f)), y,
                pc(2.245904002e8f)), y, pc(3.733650367e10f)), y, pc(4.244419664e12f)), y,
                pc(2.499580570e14f));
    // paired reciprocals: 1/(d0*d1), 1/(d2*d3)
    pf d01 = pmul(d0, d1), d23 = pmul(d2, d3);
    float ta, tb; up2(d01, ta, tb);
    pf i01 = pk2(__fdividef(1.0f, ta), __fdividef(1.0f, tb));
    up2(d23, ta, tb);
    pf i23 = pk2(__fdividef(1.0f, ta), __fdividef(1.0f, tb));
    pf j0s = pmul(pmul(n0, d1), i01);
    pf j1s = pmul(pmul(n1, d0), i01);
    pf y0s = pfma(pmul(j0s, lg), pc(TWO_OVER_PI), pmul(pmul(n2, d3), i23));
    // y1s = n3*d2*i23 + 2/pi*(j1s*lg - 1/x)
    pf y1s = pfma(pfma(j1s, lg, pneg(rx)), pc(TWO_OVER_PI), pmul(pmul(n3, d2), i23));

    // ---------- big path ----------
    pf z  = pmul(pc(8.0f), rx);
    pf y2 = pmul(z, z);
    pf pp0 = pfma(pfma(pfma(pfma(pc(0.2093887211e-6f), y2, pc(-0.2073370639e-5f)), y2,
                 pc(0.2734510407e-4f)), y2, pc(-0.1098628627e-2f)), y2, pc(1.0f));
    pf qq0 = pfma(pfma(pfma(pfma(pc(-0.934935152e-7f), y2, pc(0.7621095161e-6f)), y2,
                 pc(-0.6911147651e-5f)), y2, pc(0.1430488765e-3f)), y2, pc(-0.1562499995e-1f));
    pf pp1 = pfma(pfma(pfma(pfma(pc(-0.240337019e-6f), y2, pc(0.2457520174e-5f)), y2,
                 pc(-0.3516396496e-4f)), y2, pc(0.183105e-2f)), y2, pc(1.0f));
    pf qq1 = pfma(pfma(pfma(pfma(pc(0.105787412e-6f), y2, pc(-0.88228987e-6f)), y2,
                 pc(0.8449199096e-5f)), y2, pc(-0.2002690873e-3f)), y2, pc(0.04687499995f));

    // sincos(x - pi/4): q = round(x*2/pi - 0.5); r = x - (q+0.5)*pi/2
    pf v  = pmul(px, pc(0.6366197723675814f));
    pf t  = padd(padd(v, pc(-0.5f)), pc(MAGICF));
    float tf0, tf1; up2(t, tf0, tf1);
    int nq0 = __float_as_int(tf0) & 3;
    int nq1 = __float_as_int(tf1) & 3;
    pf qf = padd(t, pc(-MAGICF));
    pf qh = padd(qf, pc(0.5f));
    pf r  = pfma(qh, pc(-1.5703125f), px);
    r = pfma(qh, pc(-4.837512969970703125e-4f), r);
    r = pfma(qh, pc(-7.54978995489188216e-8f), r);
    pf rr = pmul(r, r);
    pf sp = pfma(pfma(pc(-1.9515295891e-4f), rr, pc(8.3321608736e-3f)), rr, pc(-1.6666654611e-1f));
    pf s_ = pfma(pmul(rr, r), sp, r);
    pf cp = pfma(pfma(pfma(pc(2.443315711e-5f), rr, pc(-1.388731625e-3f)), rr,
                pc(4.166664568e-2f)), rr, pc(-0.5f));
    pf c_ = pfma(cp, rr, pc(1.0f));
    float sl0, sl1, cl0, cl1; up2(s_, sl0, sl1); up2(c_, cl0, cl1);
    float S0, C0, S1, C1;
    quadfix(nq0, sl0, cl0, S0, C0);
    quadfix(nq1, sl1, cl1, S1, C1);
    pf S = pk2(S0, S1), C = pk2(C0, C1);

    pf amp = pmul(rs, pc(SQRT_2_PI));
    pf u  = pmul(amp, C), w_ = pmul(amp, S);
    pf uz = pmul(u, z),  wz = pmul(w_, z);
    pf j0b = pfma(pneg(wz), qq0, pmul(u, pp0));   // u*p0 - wz*q0
    pf y0b = pfma(uz, qq0, pmul(w_, pp0));        // w*p0 + uz*q0
    pf j1b = pfma(uz, qq1, pmul(w_, pp1));        // w*p1 + uz*q1
    pf y1b = pfma(wz, qq1, pmul(pneg(u), pp1));   // wz*q1 - u*p1

    // ---------- blend ----------
    pf m = pk2(x0 < 8.0f ? 1.0f : 0.0f, x1 < 8.0f ? 1.0f : 0.0f);
    J0 = pfma(m, psub(j0s, j0b), j0b);
    J1 = pfma(m, psub(j1s, j1b), j1b);
    Y0 = pfma(m, psub(y0s, y0b), y0b);
    Y1 = pfma(m, psub(y1s, y1b), y1b);
}

// Shell transfer matrix quartet [[a, ib],[ic, d]] (a,b,c,d real, packed).
__device__ __forceinline__ void shell_pair(pf k, pf p, pf ip, float r0, float r1,
                                           pf& a, pf& b, pf& c, pf& d) {
    pf x0 = pmul(k, pc(r0));
    pf x1 = pmul(k, pc(r1));
    pf ja, j1a, ya, y1a, jb, j1b, yb, y1b;
    bessel4_pair(x0, ja, j1a, ya, y1a);
    bessel4_pair(x1, jb, j1b, yb, y1b);
    pf pref = pmul(x0, pc(PI_2f));
    a = pmul(pref, psub(pmul(j1a, yb), pmul(y1a, jb)));
    b = pmul(pmul(pref, ip), psub(pmul(ja, yb), pmul(ya, jb)));
    c = pmul(pneg(pmul(p, pref)), psub(pmul(y1a, j1b), pmul(j1a, y1b)));
    d = pmul(pref, psub(pmul(ya, j1b), pmul(ja, y1b)));
}

// c1(z) = -(J1+iY1)/(J0+iY0)  (packed re/im)
__device__ __forceinline__ void cfac_pair(pf z, pf& re, pf& im) {
    pf j0v, j1v, y0v, y1v;
    bessel4_pair(z, j0v, j1v, y0v, y1v);
    pf den = pfma(j0v, j0v, pmul(y0v, y0v));
    float ta, tb; up2(den, ta, tb);
    pf inv = pk2(__fdividef(1.0f, ta), __fdividef(1.0f, tb));
    re = pmul(pneg(pfma(j1v, j0v, pmul(y1v, y0v))), inv);
    im = pmul(psub(pmul(j1v, y0v), pmul(y1v, j0v)), inv);
}

__global__ void __launch_bounds__(256)
annular_tm_kernel(const float* __restrict__ omega,
                  const float* __restrict__ eps,
                  const float* __restrict__ mu,
                  const float* __restrict__ rho,
                  float* __restrict__ out, int W) {
    int half = W >> 1;
    int i = blockIdx.x * blockDim.x + threadIdx.x;
    if (i >= half) return;
    int j = i + half;

    pf w = pk2(omega[i], omega[j]);

    // rho scalars
    float rIn[6], rOut[6];
    #pragma unroll
    for (int l = 0; l < 6; l++) { rIn[l] = __ldg(&rho[2*l]); rOut[l] = __ldg(&rho[2*l+1]); }

    // per-layer wavenumber/impedance: rs = rsqrt(e*m); k = w*e*m*rs; p = e*rs; 1/p = m*rs
    pf A, B, C, D;
    {
        pf e = pk2(eps[1*W + i], eps[1*W + j]);
        pf m = pk2(mu[1*W + i],  mu[1*W + j]);
        pf em = pmul(e, m);
        float a0, a1; up2(em, a0, a1);
        pf rse = pk2(rsqrtf(a0), rsqrtf(a1));
        pf k = pmul(pmul(w, em), rse);
        pf p = pmul(e, rse);
        pf ip = pmul(m, rse);
        shell_pair(k, p, ip, rIn[1], rOut[1], A, B, C, D);
    }
    #pragma unroll
    for (int l = 2; l <= 4; l++) {
        pf e = pk2(eps[l*W + i], eps[l*W + j]);
        pf m = pk2(mu[l*W + i],  mu[l*W + j]);
        pf em = pmul(e, m);
        float a0, a1; up2(em, a0, a1);
        pf rse = pk2(rsqrtf(a0), rsqrtf(a1));
        pf k = pmul(pmul(w, em), rse);
        pf p = pmul(e, rse);
        pf ip = pmul(m, rse);
        pf a, b, c, d;
        shell_pair(k, p, ip, rIn[l], rOut[l], a, b, c, d);
        pf A2 = psub(pmul(A, a), pmul(B, c));
        pf B2 = pfma(A, b, pmul(B, d));
        pf C2 = pfma(C, a, pmul(D, c));
        pf D2 = pfma(D, d, pneg(pmul(C, b)));
        A = A2; B = B2; C = C2; D = D2;
    }

    // boundary media 0 and 5
    pf e0 = pk2(eps[0*W + i], eps[0*W + j]);
    pf m0 = pk2(mu[0*W + i],  mu[0*W + j]);
    pf eL = pk2(eps[5*W + i], eps[5*W + j]);
    pf mL = pk2(mu[5*W + i],  mu[5*W + j]);
    pf em0 = pmul(e0, m0), emL = pmul(eL, mL);
    float b0a, b0b, bLa, bLb; up2(em0, b0a, b0b); up2(emL, bLa, bLb);
    pf rs0 = pk2(rsqrtf(b0a), rsqrtf(b0b));
    pf rsL = pk2(rsqrtf(bLa), rsqrtf(bLb));
    pf k0 = pmul(pmul(w, em0), rs0);
    pf pz0 = pmul(e0, rs0);
    pf kL = pmul(pmul(w, emL), rsL);
    pf pzL = pmul(eL, rsL);

    pf c01r, c01i, cLr, cLi;
    cfac_pair(pmul(k0, pc(rOut[0])), c01r, c01i);
    cfac_pair(pmul(kL, pc(rIn[5])),  cLr,  cLi);
    pf c12r = cLr, c12i = pneg(cLi);     // c1_2 = conj(c1L)

    // a1 = p0*c01.x ; a2 = p0*c01.y   (c02 = conj(c01))
    pf a1 = pmul(pz0, c01r);
    pf a2 = pmul(pz0, c01i);

    // num = iC + i*p0*c02*A - i*pL*c12*(D - p0*c02*B)
    pf Tr = psub(D, pmul(a1, B));
    pf Ti = pmul(a2, B);                               // -p0*c02.y*B = +a2*B
    pf Vr = psub(pmul(c12r, Tr), pmul(c12i, Ti));
    pf Vi = pfma(c12r, Ti, pmul(c12i, Tr));
    pf Ur = pneg(pmul(pzL, Vi));
    pf Ui = pmul(pzL, Vr);
    pf numr = psub(pmul(A, a2), Ur);
    pf numi = psub(padd(C, pmul(A, a1)), Ui);

    // den = -i*p0*c01*A - iC - i*pL*c12*(p0*c01*B - D)
    pf Sr = psub(pmul(a1, B), D);
    pf Si = pmul(a2, B);
    pf Wr = psub(pmul(c12r, Sr), pmul(c12i, Si));
    pf Wi = pfma(c12r, Si, pmul(c12i, Sr));
    pf Xr = pneg(pmul(pzL, Wi));
    pf Xi = pmul(pzL, Wr);
    pf denr = psub(pmul(A, a2), Xr);
    pf deni = pneg(padd(padd(pmul(A, a1), C), Xi));

    pf n2p = pfma(numr, numr, pmul(numi, numi));
    pf d2p = pfma(denr, denr, pmul(deni, deni));
    float na, nb, da, db;
    up2(n2p, na, nb); up2(d2p, da, db);
    out[i] = na * __fdividef(1.0f, da);
    out[j] = nb * __fdividef(1.0f, db);
}

extern "C" void kernel_launch(void* const* d_in, const int* in_sizes, int n_in,
                              void* d_out, int out_size) {
    const float* omega = (const float*)d_in[0];
    const float* eps   = (const float*)d_in[1];
    const float* mu    = (const float*)d_in[2];
    const float* rho   = (const float*)d_in[3];
    float* out = (float*)d_out;
    int W = in_sizes[0];
    int half = W >> 1;
    int threads = 256;
    int blocks = (half + threads - 1) / threads;
    annular_tm_kernel<<<blocks, threads>>>(omega, eps, mu, rho, out, W);
}